// round 1
// baseline (speedup 1.0000x reference)
#include <cuda_runtime.h>

// MultiScaleDeformableAttention
// value:               (8, 22223, 8, 32) f32
// sampling_locations:  (8, 900, 8, 4, 4, 2) f32
// attention_weights:   (8, 900, 8, 4, 4) f32
// out:                 (8, 900, 256) f32  == (b, q, h, d)

#define BS   8
#define NQ   900
#define NH   8
#define D    32
#define NL   4
#define NPT  4
#define NUM_KEYS 22223

__device__ __constant__ int c_H[NL]     = {100, 50, 25, 13};
__device__ __constant__ int c_W[NL]     = {167, 84, 42, 21};
__device__ __constant__ int c_START[NL] = {0, 16700, 20900, 21950};

__global__ void __launch_bounds__(256) msda_kernel(
    const float* __restrict__ value,
    const float* __restrict__ loc,
    const float* __restrict__ aw,
    float* __restrict__ out)
{
    const int tid = blockIdx.x * blockDim.x + threadIdx.x;
    const int total = BS * NQ * NH * (D / 4);
    if (tid >= total) return;

    const int chunk = tid & 7;        // which float4 of the 32-channel vector
    const int bqh   = tid >> 3;
    const int h     = bqh % NH;
    const int bq    = bqh / NH;
    const int q     = bq % NQ;
    const int b     = bq / NQ;

    // sampling locations / weights for this (b,q,h)
    const float* loc_p = loc + (((b * NQ + q) * NH + h) * NL * NPT) * 2;
    const float* aw_p  = aw  + (((b * NQ + q) * NH + h) * NL * NPT);

    // value base for this (b, h), offset to this thread's channel chunk
    const float* vbase = value + (b * NUM_KEYS * NH + h) * D + chunk * 4;

    float4 acc = make_float4(0.f, 0.f, 0.f, 0.f);

    #pragma unroll
    for (int l = 0; l < NL; ++l) {
        const int H = c_H[l];
        const int W = c_W[l];
        const float* vlvl = vbase + c_START[l] * (NH * D);

        #pragma unroll
        for (int p = 0; p < NPT; ++p) {
            const int s = l * NPT + p;
            const float lx = __ldg(&loc_p[s * 2 + 0]);
            const float ly = __ldg(&loc_p[s * 2 + 1]);
            const float wa = __ldg(&aw_p[s]);

            const float x = lx * (float)W - 0.5f;
            const float y = ly * (float)H - 0.5f;
            const float xf = floorf(x);
            const float yf = floorf(y);
            const int x0 = (int)xf;
            const int y0 = (int)yf;
            const float tx = x - xf;
            const float ty = y - yf;

            const float w00 = (1.f - tx) * (1.f - ty) * wa;
            const float w10 = tx * (1.f - ty) * wa;
            const float w01 = (1.f - tx) * ty * wa;
            const float w11 = tx * ty * wa;

            const bool vx0 = (x0 >= 0) && (x0 < W);
            const bool vx1 = (x0 + 1 >= 0) && (x0 + 1 < W);
            const bool vy0 = (y0 >= 0) && (y0 < H);
            const bool vy1 = (y0 + 1 >= 0) && (y0 + 1 < H);

            const int row0 = y0 * W;
            const int row1 = row0 + W;

            float4 v00 = make_float4(0.f,0.f,0.f,0.f);
            float4 v10 = make_float4(0.f,0.f,0.f,0.f);
            float4 v01 = make_float4(0.f,0.f,0.f,0.f);
            float4 v11 = make_float4(0.f,0.f,0.f,0.f);

            if (vy0 && vx0) v00 = *(const float4*)(vlvl + (row0 + x0    ) * (NH * D));
            if (vy0 && vx1) v10 = *(const float4*)(vlvl + (row0 + x0 + 1) * (NH * D));
            if (vy1 && vx0) v01 = *(const float4*)(vlvl + (row1 + x0    ) * (NH * D));
            if (vy1 && vx1) v11 = *(const float4*)(vlvl + (row1 + x0 + 1) * (NH * D));

            acc.x += w00 * v00.x + w10 * v10.x + w01 * v01.x + w11 * v11.x;
            acc.y += w00 * v00.y + w10 * v10.y + w01 * v01.y + w11 * v11.y;
            acc.z += w00 * v00.z + w10 * v10.z + w01 * v01.z + w11 * v11.z;
            acc.w += w00 * v00.w + w10 * v10.w + w01 * v01.w + w11 * v11.w;
        }
    }

    float* op = out + ((b * NQ + q) * NH + h) * D + chunk * 4;
    *(float4*)op = acc;
}

extern "C" void kernel_launch(void* const* d_in, const int* in_sizes, int n_in,
                              void* d_out, int out_size)
{
    const float* value = (const float*)d_in[0];
    const float* loc   = (const float*)d_in[1];
    const float* aw    = (const float*)d_in[2];
    float* out = (float*)d_out;

    const int total = BS * NQ * NH * (D / 4);   // 460800
    const int block = 256;
    const int grid  = (total + block - 1) / block;
    msda_kernel<<<grid, block>>>(value, loc, aw, out);
}